// round 7
// baseline (speedup 1.0000x reference)
#include <cuda_runtime.h>

#define NN 100000
#define NP 100096              // padded rows (multiple of 64) for GEMM stores
#define EE 1600000
#define DD 128
#define ET (EE + NN)

// ---------------- scratch (static device globals; no allocations) ----------
__device__ int   g_flag;           // nonzero => edge_index is int32
__device__ int   g_deg[NN];        // degree over row incl. self loop
__device__ int   g_cnt[NN];        // in-degree over col incl. self loop
__device__ int   g_off[NN + 1];    // CSR offsets by col
__device__ int   g_cur[NN];        // fill cursors
__device__ float g_dis[NN];        // deg^-0.5
__device__ float g_s[NN];          // s_i = sum_j norm_ij (bias folding)
__device__ int2  g_edges[ET];      // (src, weight-as-bits), grouped by dst
__device__ float g_P[(size_t)NP * DD];  // projected features (GEMM out, pull in)
__device__ float g_H[(size_t)NN * DD];  // hidden features (pull out, GEMM in)

// ---------------- init + dtype detect ---------------------------------------
// Block 0 also detects int32-vs-int64: for int64 all high 32-bit words are 0.
__global__ void k_init(const int* __restrict__ ei32) {
    int i = blockIdx.x * blockDim.x + threadIdx.x;
    if (i < NN) { g_deg[i] = 1; g_cnt[i] = 1; g_cur[i] = 0; g_s[i] = 0.f; }
    if (blockIdx.x == 0) {
        __shared__ int sred[256];
        int t = threadIdx.x;
        int w = 0;
        for (int j = t; j < 4096; j += 256) w |= ei32[2 * j + 1];
        sred[t] = w;
        __syncthreads();
        for (int d = 128; d > 0; d >>= 1) {
            if (t < d) sred[t] |= sred[t + d];
            __syncthreads();
        }
        if (t == 0) g_flag = (sred[0] != 0) ? 1 : 0;
    }
}

// ---------------- degree counting (2 edges per thread) ----------------------
__global__ void k_count(const void* __restrict__ ei) {
    int e2 = blockIdx.x * blockDim.x + threadIdx.x;   // edge pair index
    if (e2 * 2 >= EE) return;
    bool is32 = (g_flag != 0);
    int r0, r1, c0, c1;
    if (is32) {
        int2 rr = ((const int2*)ei)[e2];
        int2 cc = ((const int2*)((const int*)ei + EE))[e2];
        r0 = rr.x; r1 = rr.y; c0 = cc.x; c1 = cc.y;
    } else {
        longlong2 rr = ((const longlong2*)ei)[e2];
        longlong2 cc = ((const longlong2*)((const long long*)ei + EE))[e2];
        r0 = (int)rr.x; r1 = (int)rr.y; c0 = (int)cc.x; c1 = (int)cc.y;
    }
    if ((unsigned)r0 < NN) atomicAdd(&g_deg[r0], 1);
    if ((unsigned)r1 < NN) atomicAdd(&g_deg[r1], 1);
    if ((unsigned)c0 < NN) atomicAdd(&g_cnt[c0], 1);
    if ((unsigned)c1 < NN) atomicAdd(&g_cnt[c1], 1);
}

// exclusive scan of g_cnt -> g_off, plus g_dis = deg^-0.5; one block of 1024
__global__ __launch_bounds__(1024) void k_scan() {
    const int T = 1024;
    const int C = (NN + T - 1) / T;   // 98
    int t = threadIdx.x;
    int base = t * C;
    int s = 0;
    for (int j = 0; j < C; j++) {
        int idx = base + j;
        if (idx < NN) {
            s += g_cnt[idx];
            g_dis[idx] = rsqrtf((float)g_deg[idx]);
        }
    }
    __shared__ int ps[T];
    ps[t] = s;
    __syncthreads();
    for (int d = 1; d < T; d <<= 1) {
        int v = (t >= d) ? ps[t - d] : 0;
        __syncthreads();
        ps[t] += v;
        __syncthreads();
    }
    int run = ps[t] - s;  // exclusive prefix
    for (int j = 0; j < C; j++) {
        int idx = base + j;
        if (idx < NN) { g_off[idx] = run; run += g_cnt[idx]; }
    }
    if (t == T - 1) g_off[NN] = run;
}

// scatter edges (and self loops) into CSR-by-col with fused weights;
// also accumulate s_i = sum of weights per target (bias folding).
__device__ __forceinline__ void fill_one(int r, int c) {
    if ((unsigned)r < NN && (unsigned)c < NN) {
        float w = g_dis[r] * g_dis[c];
        int pos = g_off[c] + atomicAdd(&g_cur[c], 1);
        g_edges[pos] = make_int2(r, __float_as_int(w));
        atomicAdd(&g_s[c], w);
    }
}

__global__ void k_fill(const void* __restrict__ ei) {
    int e2 = blockIdx.x * blockDim.x + threadIdx.x;
    const int HALF = EE / 2;
    bool is32 = (g_flag != 0);
    if (e2 < HALF) {
        int r0, r1, c0, c1;
        if (is32) {
            int2 rr = ((const int2*)ei)[e2];
            int2 cc = ((const int2*)((const int*)ei + EE))[e2];
            r0 = rr.x; r1 = rr.y; c0 = cc.x; c1 = cc.y;
        } else {
            longlong2 rr = ((const longlong2*)ei)[e2];
            longlong2 cc = ((const longlong2*)((const long long*)ei + EE))[e2];
            r0 = (int)rr.x; r1 = (int)rr.y; c0 = (int)cc.x; c1 = (int)cc.y;
        }
        fill_one(r0, c0);
        fill_one(r1, c1);
    } else if (e2 < HALF + NN) {
        int i = e2 - HALF;          // self loop
        float d = g_dis[i];
        float w = d * d;
        int pos = g_off[i] + atomicAdd(&g_cur[i], 1);
        g_edges[pos] = make_int2(i, __float_as_int(w));
        atomicAdd(&g_s[i], w);
    }
}

// ---------------- GEMM: g_P[N,128] = A[N,128] @ W^T  (no bias) -------------
// SIMT fp32: BM=64, BN=128, BK=32, 256 threads, 4x8 register tile.
template <bool USE_H>
__global__ __launch_bounds__(256) void k_gemm(const float* __restrict__ Ax,
                                              const float* __restrict__ Wm) {
    __shared__ __align__(16) float sA[64][36];
    __shared__ __align__(16) float sW[32][132];

    const float* __restrict__ A = USE_H ? (const float*)g_H : Ax;

    int t = threadIdx.x;
    int trow = t >> 4;   // 0..15 -> rows trow*4..+3
    int tcol = t & 15;   // 0..15 -> cols tcol*8..+7
    int rowBase = blockIdx.x * 64;

    float acc[4][8];
#pragma unroll
    for (int r = 0; r < 4; r++)
#pragma unroll
        for (int c = 0; c < 8; c++) acc[r][c] = 0.f;

    for (int kt = 0; kt < 4; kt++) {
#pragma unroll
        for (int i = 0; i < 2; i++) {
            int idx = t + i * 256;
            int r = idx >> 3, c4 = idx & 7;
            int gr = rowBase + r;
            float4 v = make_float4(0.f, 0.f, 0.f, 0.f);
            if (gr < NN)
                v = *(const float4*)(A + (size_t)gr * DD + kt * 32 + c4 * 4);
            *(float4*)&sA[r][c4 * 4] = v;
        }
#pragma unroll
        for (int i = 0; i < 4; i++) {
            int idx = t + i * 256;
            int d = idx >> 3, k4 = idx & 7;
            float4 v = *(const float4*)(Wm + d * DD + kt * 32 + k4 * 4);
            sW[k4 * 4 + 0][d] = v.x;
            sW[k4 * 4 + 1][d] = v.y;
            sW[k4 * 4 + 2][d] = v.z;
            sW[k4 * 4 + 3][d] = v.w;
        }
        __syncthreads();

#pragma unroll
        for (int k4 = 0; k4 < 8; k4++) {
            float4 af[4];
#pragma unroll
            for (int r = 0; r < 4; r++)
                af[r] = *(float4*)&sA[trow * 4 + r][k4 * 4];
            const float* ap = (const float*)af;
#pragma unroll
            for (int kk = 0; kk < 4; kk++) {
                float4 b0 = *(float4*)&sW[k4 * 4 + kk][tcol * 8];
                float4 b1 = *(float4*)&sW[k4 * 4 + kk][tcol * 8 + 4];
                float bw[8] = {b0.x, b0.y, b0.z, b0.w, b1.x, b1.y, b1.z, b1.w};
#pragma unroll
                for (int r = 0; r < 4; r++) {
                    float a = ap[r * 4 + kk];
#pragma unroll
                    for (int c = 0; c < 8; c++) acc[r][c] = fmaf(a, bw[c], acc[r][c]);
                }
            }
        }
        __syncthreads();
    }

#pragma unroll
    for (int r = 0; r < 4; r++) {
        int grow = rowBase + trow * 4 + r;
        if (grow < NN) {
            float4 o0 = make_float4(acc[r][0], acc[r][1], acc[r][2], acc[r][3]);
            float4 o1 = make_float4(acc[r][4], acc[r][5], acc[r][6], acc[r][7]);
            float* Crow = g_P + (size_t)grow * DD + tcol * 8;
            *(float4*)Crow = o0;
            *(float4*)(Crow + 4) = o1;
        }
    }
}

// ---------------- pull aggregation + bias + ReLU ----------------------------
// one warp per node; lane owns cols lane*4..+3 (float4). Reads g_P.
// out_i = relu( sum_j w_ij * p_j  +  b * s_i )
template <bool TO_H>
__global__ __launch_bounds__(256) void k_pull(const float* __restrict__ bias,
                                              float* __restrict__ Ox) {
    int gw = (blockIdx.x * blockDim.x + threadIdx.x) >> 5;
    int lane = threadIdx.x & 31;
    if (gw >= NN) return;
    int s = g_off[gw];
    int e = g_off[gw + 1];
    const float4* __restrict__ Pb = (const float4*)g_P;
    float4 acc = make_float4(0.f, 0.f, 0.f, 0.f);
    int j = s;
    for (; j + 2 <= e; j += 2) {
        int2 e0 = g_edges[j];
        int2 e1 = g_edges[j + 1];
        float4 v0 = Pb[(size_t)e0.x * 32 + lane];
        float4 v1 = Pb[(size_t)e1.x * 32 + lane];
        float w0 = __int_as_float(e0.y);
        float w1 = __int_as_float(e1.y);
        acc.x += w0 * v0.x + w1 * v1.x;
        acc.y += w0 * v0.y + w1 * v1.y;
        acc.z += w0 * v0.z + w1 * v1.z;
        acc.w += w0 * v0.w + w1 * v1.w;
    }
    if (j < e) {
        int2 e0 = g_edges[j];
        float4 v0 = Pb[(size_t)e0.x * 32 + lane];
        float w0 = __int_as_float(e0.y);
        acc.x += w0 * v0.x;
        acc.y += w0 * v0.y;
        acc.z += w0 * v0.z;
        acc.w += w0 * v0.w;
    }
    float si = g_s[gw];
    float4 b4 = *(const float4*)(bias + lane * 4);
    float4 r = make_float4(fmaxf(acc.x + b4.x * si, 0.f),
                           fmaxf(acc.y + b4.y * si, 0.f),
                           fmaxf(acc.z + b4.z * si, 0.f),
                           fmaxf(acc.w + b4.w * si, 0.f));
    float4* Ob = TO_H ? (float4*)g_H : (float4*)Ox;
    Ob[(size_t)gw * 32 + lane] = r;
}

// ---------------- launch ----------------------------------------------------
extern "C" void kernel_launch(void* const* d_in, const int* in_sizes, int n_in,
                              void* d_out, int out_size) {
    const float* x  = (const float*)d_in[0];
    const void*  ei = d_in[1];                 // int32 or int64, detected on device
    const float* W1 = (const float*)d_in[2];
    const float* b1 = (const float*)d_in[3];
    const float* W2 = (const float*)d_in[4];
    const float* b2 = (const float*)d_in[5];
    const float* W3 = (const float*)d_in[6];
    const float* b3 = (const float*)d_in[7];
    float* out = (float*)d_out;

    // lazily created on the first (uncaptured correctness) call; reused after.
    static cudaStream_t side = nullptr;
    static cudaEvent_t evInit = nullptr, evFill = nullptr;
    if (!side) {
        cudaStreamCreateWithFlags(&side, cudaStreamNonBlocking);
        cudaEventCreateWithFlags(&evInit, cudaEventDisableTiming);
        cudaEventCreateWithFlags(&evFill, cudaEventDisableTiming);
    }

    const int TB = 256;
    const int GB = (NN + 63) / 64;             // gemm blocks (1563)
    const int PB = (NN * 32 + TB - 1) / TB;    // pull blocks (warp per node)
    const int CB = (EE / 2 + TB - 1) / TB;     // count blocks (2 edges/thread)
    const int FB = (EE / 2 + NN + TB - 1) / TB;// fill blocks

    // init (main), then fork: edge pipeline on side stream, gemm1 on main.
    k_init<<<(NN + TB - 1) / TB, TB>>>((const int*)ei);
    cudaEventRecord(evInit, 0);
    cudaStreamWaitEvent(side, evInit, 0);

    k_count<<<CB, TB, 0, side>>>(ei);
    k_scan <<<1, 1024, 0, side>>>();
    k_fill <<<FB, TB, 0, side>>>(ei);
    cudaEventRecord(evFill, side);

    k_gemm<false><<<GB, 256>>>(x, W1);         // concurrent with edge pipeline
    cudaStreamWaitEvent(0, evFill, 0);         // join before pull1

    k_pull<true><<<PB, 256>>>(b1, nullptr);
    k_gemm<true><<<GB, 256>>>(nullptr, W2);
    k_pull<true><<<PB, 256>>>(b2, nullptr);
    k_gemm<true><<<GB, 256>>>(nullptr, W3);
    k_pull<false><<<PB, 256>>>(b3, out);
}

// round 9
// speedup vs baseline: 1.0655x; 1.0655x over previous
#include <cuda_runtime.h>
#include <cstdint>

#define NN 100000
#define NP 100096              // padded rows (multiple of 64) for unguarded access
#define EE 1600000
#define DD 128
#define ET (EE + NN)

// ---------------- scratch (static device globals; no allocations) ----------
__device__ int   g_flag;           // nonzero => edge_index is int32
__device__ int   g_deg[NN];        // degree over row incl. self loop
__device__ int   g_cnt[NN];        // in-degree over col incl. self loop
__device__ int   g_off[NN + 1];    // CSR offsets by col
__device__ int   g_cur[NN];        // fill cursors
__device__ float g_dis[NN];        // deg^-0.5
__device__ float g_s[NN];          // s_i = sum_j norm_ij (bias folding)
__device__ int2  g_edges[ET];      // (src, weight-as-bits), grouped by dst
__device__ float g_P[(size_t)NP * DD];  // projected features (GEMM out, pull in)
__device__ float g_H[(size_t)NP * DD];  // hidden features (pull out, GEMM in)

// ---------------- init + dtype detect ---------------------------------------
// Block 0 also detects int32-vs-int64: for int64 all high 32-bit words are 0.
__global__ void k_init(const int* __restrict__ ei32) {
    int i = blockIdx.x * blockDim.x + threadIdx.x;
    if (i < NN) { g_deg[i] = 1; g_cnt[i] = 1; g_cur[i] = 0; }
    if (blockIdx.x == 0) {
        __shared__ int sred[256];
        int t = threadIdx.x;
        int w = 0;
        for (int j = t; j < 4096; j += 256) w |= ei32[2 * j + 1];
        sred[t] = w;
        __syncthreads();
        for (int d = 128; d > 0; d >>= 1) {
            if (t < d) sred[t] |= sred[t + d];
            __syncthreads();
        }
        if (t == 0) g_flag = (sred[0] != 0) ? 1 : 0;
    }
}

// ---------------- degree counting (2 edges per thread) ----------------------
__global__ void k_count(const void* __restrict__ ei) {
    int e2 = blockIdx.x * blockDim.x + threadIdx.x;
    if (e2 * 2 >= EE) return;
    bool is32 = (g_flag != 0);
    int r0, r1, c0, c1;
    if (is32) {
        int2 rr = ((const int2*)ei)[e2];
        int2 cc = ((const int2*)((const int*)ei + EE))[e2];
        r0 = rr.x; r1 = rr.y; c0 = cc.x; c1 = cc.y;
    } else {
        longlong2 rr = ((const longlong2*)ei)[e2];
        longlong2 cc = ((const longlong2*)((const long long*)ei + EE))[e2];
        r0 = (int)rr.x; r1 = (int)rr.y; c0 = (int)cc.x; c1 = (int)cc.y;
    }
    if ((unsigned)r0 < NN) atomicAdd(&g_deg[r0], 1);
    if ((unsigned)r1 < NN) atomicAdd(&g_deg[r1], 1);
    if ((unsigned)c0 < NN) atomicAdd(&g_cnt[c0], 1);
    if ((unsigned)c1 < NN) atomicAdd(&g_cnt[c1], 1);
}

// exclusive scan of g_cnt -> g_off, plus g_dis = deg^-0.5; one block of 1024
__global__ __launch_bounds__(1024) void k_scan() {
    const int T = 1024;
    const int C = (NN + T - 1) / T;   // 98
    int t = threadIdx.x;
    int base = t * C;
    int s = 0;
    for (int j = 0; j < C; j++) {
        int idx = base + j;
        if (idx < NN) {
            s += g_cnt[idx];
            g_dis[idx] = rsqrtf((float)g_deg[idx]);
        }
    }
    __shared__ int ps[T];
    ps[t] = s;
    __syncthreads();
    for (int d = 1; d < T; d <<= 1) {
        int v = (t >= d) ? ps[t - d] : 0;
        __syncthreads();
        ps[t] += v;
        __syncthreads();
    }
    int run = ps[t] - s;  // exclusive prefix
    for (int j = 0; j < C; j++) {
        int idx = base + j;
        if (idx < NN) { g_off[idx] = run; run += g_cnt[idx]; }
    }
    if (t == T - 1) g_off[NN] = run;
}

// scatter edges (and self loops) into CSR-by-col with fused weights
__device__ __forceinline__ void fill_one(int r, int c) {
    if ((unsigned)r < NN && (unsigned)c < NN) {
        float w = g_dis[r] * g_dis[c];
        int pos = g_off[c] + atomicAdd(&g_cur[c], 1);
        g_edges[pos] = make_int2(r, __float_as_int(w));
    }
}

__global__ void k_fill(const void* __restrict__ ei) {
    int e2 = blockIdx.x * blockDim.x + threadIdx.x;
    const int HALF = EE / 2;
    bool is32 = (g_flag != 0);
    if (e2 < HALF) {
        int r0, r1, c0, c1;
        if (is32) {
            int2 rr = ((const int2*)ei)[e2];
            int2 cc = ((const int2*)((const int*)ei + EE))[e2];
            r0 = rr.x; r1 = rr.y; c0 = cc.x; c1 = cc.y;
        } else {
            longlong2 rr = ((const longlong2*)ei)[e2];
            longlong2 cc = ((const longlong2*)((const long long*)ei + EE))[e2];
            r0 = (int)rr.x; r1 = (int)rr.y; c0 = (int)cc.x; c1 = (int)cc.y;
        }
        fill_one(r0, c0);
        fill_one(r1, c1);
    } else if (e2 < HALF + NN) {
        int i = e2 - HALF;          // self loop
        float d = g_dis[i];
        int pos = g_off[i] + atomicAdd(&g_cur[i], 1);
        g_edges[pos] = make_int2(i, __float_as_int(d * d));
    }
}

// ---------------- s_i = sum of CSR-row weights (warp per node) --------------
__global__ __launch_bounds__(256) void k_sumw() {
    int gw = (blockIdx.x * blockDim.x + threadIdx.x) >> 5;
    int lane = threadIdx.x & 31;
    if (gw >= NN) return;
    int s = g_off[gw], e = g_off[gw + 1];
    float acc = 0.f;
    for (int j = s + lane; j < e; j += 32)
        acc += __int_as_float(g_edges[j].y);
#pragma unroll
    for (int d = 16; d > 0; d >>= 1)
        acc += __shfl_down_sync(0xFFFFFFFFu, acc, d);
    if (lane == 0) g_s[gw] = acc;
}

// ---------------- GEMM: g_P[N,128] = A[N,128] @ W^T  (no bias) -------------
// SIMT fp32: BM=64, BN=128, BK=32, 256 threads, 4x8 register tile.
template <bool USE_H>
__global__ __launch_bounds__(256) void k_gemm(const float* __restrict__ Ax,
                                              const float* __restrict__ Wm) {
    __shared__ __align__(16) float sA[64][36];
    __shared__ __align__(16) float sW[32][132];

    const float* __restrict__ A = USE_H ? (const float*)g_H : Ax;

    int t = threadIdx.x;
    int trow = t >> 4;   // 0..15 -> rows trow*4..+3
    int tcol = t & 15;   // 0..15 -> cols tcol*8..+7
    int rowBase = blockIdx.x * 64;
    bool guard = USE_H ? false : (rowBase + 64 > NN);   // only x is unpadded

    float acc[4][8];
#pragma unroll
    for (int r = 0; r < 4; r++)
#pragma unroll
        for (int c = 0; c < 8; c++) acc[r][c] = 0.f;

    for (int kt = 0; kt < 4; kt++) {
#pragma unroll
        for (int i = 0; i < 2; i++) {
            int idx = t + i * 256;
            int r = idx >> 3, c4 = idx & 7;
            int gr = rowBase + r;
            float4 v;
            if (guard && gr >= NN) v = make_float4(0.f, 0.f, 0.f, 0.f);
            else v = *(const float4*)(A + (size_t)gr * DD + kt * 32 + c4 * 4);
            *(float4*)&sA[r][c4 * 4] = v;
        }
#pragma unroll
        for (int i = 0; i < 4; i++) {
            int idx = t + i * 256;
            int d = idx >> 3, k4 = idx & 7;
            float4 v = *(const float4*)(Wm + d * DD + kt * 32 + k4 * 4);
            sW[k4 * 4 + 0][d] = v.x;
            sW[k4 * 4 + 1][d] = v.y;
            sW[k4 * 4 + 2][d] = v.z;
            sW[k4 * 4 + 3][d] = v.w;
        }
        __syncthreads();

#pragma unroll
        for (int k4 = 0; k4 < 8; k4++) {
            float4 af[4];
#pragma unroll
            for (int r = 0; r < 4; r++)
                af[r] = *(float4*)&sA[trow * 4 + r][k4 * 4];
            const float* ap = (const float*)af;
#pragma unroll
            for (int kk = 0; kk < 4; kk++) {
                float4 b0 = *(float4*)&sW[k4 * 4 + kk][tcol * 8];
                float4 b1 = *(float4*)&sW[k4 * 4 + kk][tcol * 8 + 4];
                float bw[8] = {b0.x, b0.y, b0.z, b0.w, b1.x, b1.y, b1.z, b1.w};
#pragma unroll
                for (int r = 0; r < 4; r++) {
                    float a = ap[r * 4 + kk];
#pragma unroll
                    for (int c = 0; c < 8; c++) acc[r][c] = fmaf(a, bw[c], acc[r][c]);
                }
            }
        }
        __syncthreads();
    }

#pragma unroll
    for (int r = 0; r < 4; r++) {
        int grow = rowBase + trow * 4 + r;      // < NP, g_P padded
        float4 o0 = make_float4(acc[r][0], acc[r][1], acc[r][2], acc[r][3]);
        float4 o1 = make_float4(acc[r][4], acc[r][5], acc[r][6], acc[r][7]);
        float* Crow = g_P + (size_t)grow * DD + tcol * 8;
        *(float4*)Crow = o0;
        *(float4*)(Crow + 4) = o1;
    }
}

// ---------------- pull aggregation + bias + ReLU ----------------------------
// one warp per node; lane owns cols lane*4..+3 (float4). Reads g_P.
// out_i = relu( sum_j w_ij * p_j  +  b * s_i )
template <bool TO_H>
__global__ __launch_bounds__(256) void k_pull(const float* __restrict__ bias,
                                              float* __restrict__ Ox) {
    int gw = (blockIdx.x * blockDim.x + threadIdx.x) >> 5;
    int lane = threadIdx.x & 31;
    if (gw >= NN) return;
    int s = g_off[gw];
    int e = g_off[gw + 1];
    const float4* __restrict__ Pb = (const float4*)g_P;
    float4 acc = make_float4(0.f, 0.f, 0.f, 0.f);
    int j = s;
    for (; j + 2 <= e; j += 2) {
        int2 e0 = g_edges[j];
        int2 e1 = g_edges[j + 1];
        float4 v0 = Pb[(size_t)e0.x * 32 + lane];
        float4 v1 = Pb[(size_t)e1.x * 32 + lane];
        float w0 = __int_as_float(e0.y);
        float w1 = __int_as_float(e1.y);
        acc.x += w0 * v0.x + w1 * v1.x;
        acc.y += w0 * v0.y + w1 * v1.y;
        acc.z += w0 * v0.z + w1 * v1.z;
        acc.w += w0 * v0.w + w1 * v1.w;
    }
    if (j < e) {
        int2 e0 = g_edges[j];
        float4 v0 = Pb[(size_t)e0.x * 32 + lane];
        float w0 = __int_as_float(e0.y);
        acc.x += w0 * v0.x;
        acc.y += w0 * v0.y;
        acc.z += w0 * v0.z;
        acc.w += w0 * v0.w;
    }
    float si = g_s[gw];
    float4 b4 = *(const float4*)(bias + lane * 4);
    float4 r = make_float4(fmaxf(acc.x + b4.x * si, 0.f),
                           fmaxf(acc.y + b4.y * si, 0.f),
                           fmaxf(acc.z + b4.z * si, 0.f),
                           fmaxf(acc.w + b4.w * si, 0.f));
    float4* Ob = TO_H ? (float4*)g_H : (float4*)Ox;
    Ob[(size_t)gw * 32 + lane] = r;
}

// ---------------- launch ----------------------------------------------------
extern "C" void kernel_launch(void* const* d_in, const int* in_sizes, int n_in,
                              void* d_out, int out_size) {
    const float* x  = (const float*)d_in[0];
    const void*  ei = d_in[1];                 // int32 or int64, detected on device
    const float* W1 = (const float*)d_in[2];
    const float* b1 = (const float*)d_in[3];
    const float* W2 = (const float*)d_in[4];
    const float* b2 = (const float*)d_in[5];
    const float* W3 = (const float*)d_in[6];
    const float* b3 = (const float*)d_in[7];
    float* out = (float*)d_out;

    const int TB = 256;
    const int CB = (EE / 2 + TB - 1) / TB;      // count blocks (2 edges/thread)
    const int FB = (EE / 2 + NN + TB - 1) / TB; // fill blocks
    const int GB = NP / 64;                     // gemm blocks (1564)
    const int PB = (NN * 32 + TB - 1) / TB;     // warp-per-node blocks

    // preprocess (single stream)
    k_init <<<(NN + TB - 1) / TB, TB>>>((const int*)ei);
    k_count<<<CB, TB>>>(ei);
    k_scan <<<1, 1024>>>();
    k_fill <<<FB, TB>>>(ei);
    k_sumw <<<PB, TB>>>();

    // layer 1: x -> P -> H
    k_gemm<false><<<GB, 256>>>(x, W1);
    k_pull<true><<<PB, 256>>>(b1, nullptr);
    // layer 2: H -> P -> H
    k_gemm<true><<<GB, 256>>>(nullptr, W2);
    k_pull<true><<<PB, 256>>>(b2, nullptr);
    // layer 3: H -> P -> out
    k_gemm<true><<<GB, 256>>>(nullptr, W3);
    k_pull<false><<<PB, 256>>>(b3, out);
}

// round 10
// speedup vs baseline: 1.0656x; 1.0000x over previous
#include <cuda_runtime.h>
#include <cstdint>

#define NN 100000
#define NP 100096              // padded rows (multiple of 64) for unguarded access
#define EE 1600000
#define DD 128
#define ET (EE + NN)

// ---------------- scratch (static device globals; no allocations) ----------
__device__ int   g_flag;           // nonzero => edge_index is int32
__device__ int   g_deg[NN];        // degree over row incl. self loop
__device__ int   g_cnt[NN];        // in-degree over col incl. self loop
__device__ int   g_off[NN + 1];    // CSR offsets by col
__device__ int   g_cur[NN];        // fill cursors
__device__ float g_dis[NN];        // deg^-0.5
__device__ float g_s[NN];          // s_i = sum_j norm_ij (bias folding)
__device__ int2  g_edges[ET];      // (src, weight-as-bits), grouped by dst
__device__ float g_P[(size_t)NP * DD];  // projected features (GEMM out, pull in)
__device__ float g_H[(size_t)NP * DD];  // hidden features (pull out, GEMM in)

// ---------------- init + dtype detect ---------------------------------------
// Block 0 also detects int32-vs-int64: for int64 all high 32-bit words are 0.
__global__ void k_init(const int* __restrict__ ei32) {
    int i = blockIdx.x * blockDim.x + threadIdx.x;
    if (i < NN) { g_deg[i] = 1; g_cnt[i] = 1; g_cur[i] = 0; }
    if (blockIdx.x == 0) {
        __shared__ int sred[256];
        int t = threadIdx.x;
        int w = 0;
        for (int j = t; j < 4096; j += 256) w |= ei32[2 * j + 1];
        sred[t] = w;
        __syncthreads();
        for (int d = 128; d > 0; d >>= 1) {
            if (t < d) sred[t] |= sred[t + d];
            __syncthreads();
        }
        if (t == 0) g_flag = (sred[0] != 0) ? 1 : 0;
    }
}

// ---------------- degree counting (2 edges per thread) ----------------------
__global__ void k_count(const void* __restrict__ ei) {
    int e2 = blockIdx.x * blockDim.x + threadIdx.x;
    if (e2 * 2 >= EE) return;
    bool is32 = (g_flag != 0);
    int r0, r1, c0, c1;
    if (is32) {
        int2 rr = ((const int2*)ei)[e2];
        int2 cc = ((const int2*)((const int*)ei + EE))[e2];
        r0 = rr.x; r1 = rr.y; c0 = cc.x; c1 = cc.y;
    } else {
        longlong2 rr = ((const longlong2*)ei)[e2];
        longlong2 cc = ((const longlong2*)((const long long*)ei + EE))[e2];
        r0 = (int)rr.x; r1 = (int)rr.y; c0 = (int)cc.x; c1 = (int)cc.y;
    }
    if ((unsigned)r0 < NN) atomicAdd(&g_deg[r0], 1);
    if ((unsigned)r1 < NN) atomicAdd(&g_deg[r1], 1);
    if ((unsigned)c0 < NN) atomicAdd(&g_cnt[c0], 1);
    if ((unsigned)c1 < NN) atomicAdd(&g_cnt[c1], 1);
}

// exclusive scan of g_cnt -> g_off, plus g_dis = deg^-0.5; one block of 1024
__global__ __launch_bounds__(1024) void k_scan() {
    const int T = 1024;
    const int C = (NN + T - 1) / T;   // 98
    int t = threadIdx.x;
    int base = t * C;
    int s = 0;
    for (int j = 0; j < C; j++) {
        int idx = base + j;
        if (idx < NN) {
            s += g_cnt[idx];
            g_dis[idx] = rsqrtf((float)g_deg[idx]);
        }
    }
    __shared__ int ps[T];
    ps[t] = s;
    __syncthreads();
    for (int d = 1; d < T; d <<= 1) {
        int v = (t >= d) ? ps[t - d] : 0;
        __syncthreads();
        ps[t] += v;
        __syncthreads();
    }
    int run = ps[t] - s;  // exclusive prefix
    for (int j = 0; j < C; j++) {
        int idx = base + j;
        if (idx < NN) { g_off[idx] = run; run += g_cnt[idx]; }
    }
    if (t == T - 1) g_off[NN] = run;
}

// scatter edges (and self loops) into CSR-by-col with fused weights
__device__ __forceinline__ void fill_one(int r, int c) {
    if ((unsigned)r < NN && (unsigned)c < NN) {
        float w = g_dis[r] * g_dis[c];
        int pos = g_off[c] + atomicAdd(&g_cur[c], 1);
        g_edges[pos] = make_int2(r, __float_as_int(w));
    }
}

__global__ void k_fill(const void* __restrict__ ei) {
    int e2 = blockIdx.x * blockDim.x + threadIdx.x;
    const int HALF = EE / 2;
    bool is32 = (g_flag != 0);
    if (e2 < HALF) {
        int r0, r1, c0, c1;
        if (is32) {
            int2 rr = ((const int2*)ei)[e2];
            int2 cc = ((const int2*)((const int*)ei + EE))[e2];
            r0 = rr.x; r1 = rr.y; c0 = cc.x; c1 = cc.y;
        } else {
            longlong2 rr = ((const longlong2*)ei)[e2];
            longlong2 cc = ((const longlong2*)((const long long*)ei + EE))[e2];
            r0 = (int)rr.x; r1 = (int)rr.y; c0 = (int)cc.x; c1 = (int)cc.y;
        }
        fill_one(r0, c0);
        fill_one(r1, c1);
    } else if (e2 < HALF + NN) {
        int i = e2 - HALF;          // self loop
        float d = g_dis[i];
        int pos = g_off[i] + atomicAdd(&g_cur[i], 1);
        g_edges[pos] = make_int2(i, __float_as_int(d * d));
    }
}

// ---------------- s_i = sum of CSR-row weights (warp per node) --------------
__global__ __launch_bounds__(256) void k_sumw() {
    int gw = (blockIdx.x * blockDim.x + threadIdx.x) >> 5;
    int lane = threadIdx.x & 31;
    if (gw >= NN) return;
    int s = g_off[gw], e = g_off[gw + 1];
    float acc = 0.f;
    for (int j = s + lane; j < e; j += 32)
        acc += __int_as_float(g_edges[j].y);
#pragma unroll
    for (int d = 16; d > 0; d >>= 1)
        acc += __shfl_down_sync(0xFFFFFFFFu, acc, d);
    if (lane == 0) g_s[gw] = acc;
}

// ---------------- GEMM: g_P[N,128] = A[N,128] @ W^T  (no bias) -------------
// SIMT fp32: BM=64, BN=128, BK=32, 256 threads, 4x8 register tile.
template <bool USE_H>
__global__ __launch_bounds__(256) void k_gemm(const float* __restrict__ Ax,
                                              const float* __restrict__ Wm) {
    __shared__ __align__(16) float sA[64][36];
    __shared__ __align__(16) float sW[32][132];

    const float* __restrict__ A = USE_H ? (const float*)g_H : Ax;

    int t = threadIdx.x;
    int trow = t >> 4;   // 0..15 -> rows trow*4..+3
    int tcol = t & 15;   // 0..15 -> cols tcol*8..+7
    int rowBase = blockIdx.x * 64;
    bool guard = USE_H ? false : (rowBase + 64 > NN);   // only x is unpadded

    float acc[4][8];
#pragma unroll
    for (int r = 0; r < 4; r++)
#pragma unroll
        for (int c = 0; c < 8; c++) acc[r][c] = 0.f;

    for (int kt = 0; kt < 4; kt++) {
#pragma unroll
        for (int i = 0; i < 2; i++) {
            int idx = t + i * 256;
            int r = idx >> 3, c4 = idx & 7;
            int gr = rowBase + r;
            float4 v;
            if (guard && gr >= NN) v = make_float4(0.f, 0.f, 0.f, 0.f);
            else v = *(const float4*)(A + (size_t)gr * DD + kt * 32 + c4 * 4);
            *(float4*)&sA[r][c4 * 4] = v;
        }
#pragma unroll
        for (int i = 0; i < 4; i++) {
            int idx = t + i * 256;
            int d = idx >> 3, k4 = idx & 7;
            float4 v = *(const float4*)(Wm + d * DD + kt * 32 + k4 * 4);
            sW[k4 * 4 + 0][d] = v.x;
            sW[k4 * 4 + 1][d] = v.y;
            sW[k4 * 4 + 2][d] = v.z;
            sW[k4 * 4 + 3][d] = v.w;
        }
        __syncthreads();

#pragma unroll
        for (int k4 = 0; k4 < 8; k4++) {
            float4 af[4];
#pragma unroll
            for (int r = 0; r < 4; r++)
                af[r] = *(float4*)&sA[trow * 4 + r][k4 * 4];
            const float* ap = (const float*)af;
#pragma unroll
            for (int kk = 0; kk < 4; kk++) {
                float4 b0 = *(float4*)&sW[k4 * 4 + kk][tcol * 8];
                float4 b1 = *(float4*)&sW[k4 * 4 + kk][tcol * 8 + 4];
                float bw[8] = {b0.x, b0.y, b0.z, b0.w, b1.x, b1.y, b1.z, b1.w};
#pragma unroll
                for (int r = 0; r < 4; r++) {
                    float a = ap[r * 4 + kk];
#pragma unroll
                    for (int c = 0; c < 8; c++) acc[r][c] = fmaf(a, bw[c], acc[r][c]);
                }
            }
        }
        __syncthreads();
    }

#pragma unroll
    for (int r = 0; r < 4; r++) {
        int grow = rowBase + trow * 4 + r;      // < NP, g_P padded
        float4 o0 = make_float4(acc[r][0], acc[r][1], acc[r][2], acc[r][3]);
        float4 o1 = make_float4(acc[r][4], acc[r][5], acc[r][6], acc[r][7]);
        float* Crow = g_P + (size_t)grow * DD + tcol * 8;
        *(float4*)Crow = o0;
        *(float4*)(Crow + 4) = o1;
    }
}

// ---------------- pull aggregation + bias + ReLU ----------------------------
// one warp per node; lane owns cols lane*4..+3 (float4). Reads g_P.
// out_i = relu( sum_j w_ij * p_j  +  b * s_i )
template <bool TO_H>
__global__ __launch_bounds__(256) void k_pull(const float* __restrict__ bias,
                                              float* __restrict__ Ox) {
    int gw = (blockIdx.x * blockDim.x + threadIdx.x) >> 5;
    int lane = threadIdx.x & 31;
    if (gw >= NN) return;
    int s = g_off[gw];
    int e = g_off[gw + 1];
    const float4* __restrict__ Pb = (const float4*)g_P;
    float4 acc = make_float4(0.f, 0.f, 0.f, 0.f);
    int j = s;
    for (; j + 2 <= e; j += 2) {
        int2 e0 = g_edges[j];
        int2 e1 = g_edges[j + 1];
        float4 v0 = Pb[(size_t)e0.x * 32 + lane];
        float4 v1 = Pb[(size_t)e1.x * 32 + lane];
        float w0 = __int_as_float(e0.y);
        float w1 = __int_as_float(e1.y);
        acc.x += w0 * v0.x + w1 * v1.x;
        acc.y += w0 * v0.y + w1 * v1.y;
        acc.z += w0 * v0.z + w1 * v1.z;
        acc.w += w0 * v0.w + w1 * v1.w;
    }
    if (j < e) {
        int2 e0 = g_edges[j];
        float4 v0 = Pb[(size_t)e0.x * 32 + lane];
        float w0 = __int_as_float(e0.y);
        acc.x += w0 * v0.x;
        acc.y += w0 * v0.y;
        acc.z += w0 * v0.z;
        acc.w += w0 * v0.w;
    }
    float si = g_s[gw];
    float4 b4 = *(const float4*)(bias + lane * 4);
    float4 r = make_float4(fmaxf(acc.x + b4.x * si, 0.f),
                           fmaxf(acc.y + b4.y * si, 0.f),
                           fmaxf(acc.z + b4.z * si, 0.f),
                           fmaxf(acc.w + b4.w * si, 0.f));
    float4* Ob = TO_H ? (float4*)g_H : (float4*)Ox;
    Ob[(size_t)gw * 32 + lane] = r;
}

// ---------------- launch ----------------------------------------------------
extern "C" void kernel_launch(void* const* d_in, const int* in_sizes, int n_in,
                              void* d_out, int out_size) {
    const float* x  = (const float*)d_in[0];
    const void*  ei = d_in[1];                 // int32 or int64, detected on device
    const float* W1 = (const float*)d_in[2];
    const float* b1 = (const float*)d_in[3];
    const float* W2 = (const float*)d_in[4];
    const float* b2 = (const float*)d_in[5];
    const float* W3 = (const float*)d_in[6];
    const float* b3 = (const float*)d_in[7];
    float* out = (float*)d_out;

    const int TB = 256;
    const int CB = (EE / 2 + TB - 1) / TB;      // count blocks (2 edges/thread)
    const int FB = (EE / 2 + NN + TB - 1) / TB; // fill blocks
    const int GB = NP / 64;                     // gemm blocks (1564)
    const int PB = (NN * 32 + TB - 1) / TB;     // warp-per-node blocks

    // preprocess (single stream)
    k_init <<<(NN + TB - 1) / TB, TB>>>((const int*)ei);
    k_count<<<CB, TB>>>(ei);
    k_scan <<<1, 1024>>>();
    k_fill <<<FB, TB>>>(ei);
    k_sumw <<<PB, TB>>>();

    // layer 1: x -> P -> H
    k_gemm<false><<<GB, 256>>>(x, W1);
    k_pull<true><<<PB, 256>>>(b1, nullptr);
    // layer 2: H -> P -> H
    k_gemm<true><<<GB, 256>>>(nullptr, W2);
    k_pull<true><<<PB, 256>>>(b2, nullptr);
    // layer 3: H -> P -> out
    k_gemm<true><<<GB, 256>>>(nullptr, W3);
    k_pull<false><<<PB, 256>>>(b3, out);
}